// round 1
// baseline (speedup 1.0000x reference)
#include <cuda_runtime.h>
#include <cstdint>

// ---------------- scratch (device globals; no allocations allowed) ----------
#define NMAX 50000
__device__ float g_xh[(size_t)NMAX * 128];   // [N, H*D] = [N,128]
__device__ float g_si[NMAX * 2];             // [N, H]
__device__ float g_sj[NMAX * 2];             // [N, H]
__device__ float g_w [NMAX * 2];             // [N, H] softmax-weight sums

// ---------------- packed fp32x2 helpers (sm_103a) ---------------------------
__device__ __forceinline__ void fma2(unsigned long long& d,
                                     unsigned long long a,
                                     unsigned long long b) {
    asm("fma.rn.f32x2 %0, %1, %2, %0;" : "+l"(d) : "l"(a), "l"(b));
}
__device__ __forceinline__ unsigned long long bcast2(float x) {
    unsigned long long r;
    asm("mov.b64 %0, {%1, %1};" : "=l"(r) : "f"(x));
    return r;
}

// ---------------- Kernel 1: xh = x @ W  (M=50000, N=128, K=128) -------------
// Tile: 128 rows x 128 cols per block, 256 threads, 8x8 outputs/thread
// (stored as 8 rows x 4 f32x2 col-pairs). W fully SMEM-resident.
#define XS_PITCH 132   // padded row pitch for transposed x tile (bank spread)

__global__ __launch_bounds__(256, 2)
void gemm_kernel(const float* __restrict__ x, const float* __restrict__ W, int N)
{
    extern __shared__ float sm[];
    float* Ws = sm;                 // 128*128 floats = 64KB
    float* Xs = sm + 128 * 128;     // 16 * 132 floats

    // load all of W (row-major [k][j]) into shared
    for (int i = threadIdx.x; i < 128 * 128 / 4; i += 256)
        ((float4*)Ws)[i] = ((const float4*)W)[i];

    const int row0 = blockIdx.x * 128;
    const int tcol = threadIdx.x & 15;   // col group: cols tcol*8 .. +7
    const int trow = threadIdx.x >> 4;   // row group: rows trow*8 .. +7

    unsigned long long acc[8][4];
#pragma unroll
    for (int m = 0; m < 8; m++)
#pragma unroll
        for (int n = 0; n < 4; n++) acc[m][n] = 0ull;

    __syncthreads();

    for (int kk = 0; kk < 128; kk += 16) {
        // stage x[row0..row0+127][kk..kk+15] transposed into Xs[k][r]
#pragma unroll
        for (int i = threadIdx.x; i < 512; i += 256) {
            int r  = i >> 2;
            int c4 = i & 3;
            int grow = row0 + r;
            float4 v = make_float4(0.f, 0.f, 0.f, 0.f);
            if (grow < N)
                v = *(const float4*)(x + (size_t)grow * 128 + kk + c4 * 4);
            int kb = c4 * 4;
            Xs[(kb + 0) * XS_PITCH + r] = v.x;
            Xs[(kb + 1) * XS_PITCH + r] = v.y;
            Xs[(kb + 2) * XS_PITCH + r] = v.z;
            Xs[(kb + 3) * XS_PITCH + r] = v.w;
        }
        __syncthreads();

#pragma unroll
        for (int k = 0; k < 16; k++) {
            const float* xr = Xs + k * XS_PITCH + trow * 8;
            float4 a0 = *(const float4*)(xr);
            float4 a1 = *(const float4*)(xr + 4);
            unsigned long long ax[8];
            ax[0] = bcast2(a0.x); ax[1] = bcast2(a0.y);
            ax[2] = bcast2(a0.z); ax[3] = bcast2(a0.w);
            ax[4] = bcast2(a1.x); ax[5] = bcast2(a1.y);
            ax[6] = bcast2(a1.z); ax[7] = bcast2(a1.w);

            const float* wr = Ws + (kk + k) * 128 + tcol * 8;
            ulonglong2 b01 = *(const ulonglong2*)(wr);
            ulonglong2 b23 = *(const ulonglong2*)(wr + 4);
            unsigned long long b[4] = { b01.x, b01.y, b23.x, b23.y };

#pragma unroll
            for (int m = 0; m < 8; m++)
#pragma unroll
                for (int n = 0; n < 4; n++)
                    fma2(acc[m][n], ax[m], b[n]);
        }
        __syncthreads();
    }

#pragma unroll
    for (int m = 0; m < 8; m++) {
        int row = row0 + trow * 8 + m;
        if (row < N) {
            ulonglong2* o = (ulonglong2*)(g_xh + (size_t)row * 128 + tcol * 8);
            o[0] = make_ulonglong2(acc[m][0], acc[m][1]);
            o[1] = make_ulonglong2(acc[m][2], acc[m][3]);
        }
    }
}

// ---------------- Kernel 2: per-node scores s_i, s_j; zero w ----------------
// one warp per node
__global__ void s_kernel(const float* __restrict__ emb,
                         const float* __restrict__ ai,  const float* __restrict__ aj,
                         const float* __restrict__ aei, const float* __restrict__ aej,
                         int N)
{
    int gw   = (blockIdx.x * blockDim.x + threadIdx.x) >> 5;
    int lane = threadIdx.x & 31;
    if (gw >= N) return;

    const float* xr = g_xh + (size_t)gw * 128;
    float x0 = xr[lane], x1 = xr[lane + 32], x2 = xr[lane + 64], x3 = xr[lane + 96];
    float e0 = emb[(size_t)gw * 64 + lane];
    float e1 = emb[(size_t)gw * 64 + lane + 32];

    float si0 = x0 * ai[lane]      + x1 * ai[lane + 32]
              + e0 * aei[lane]     + e1 * aei[lane + 32];
    float si1 = x2 * ai[lane + 64] + x3 * ai[lane + 96]
              + e0 * aei[lane + 64]+ e1 * aei[lane + 96];
    float sj0 = x0 * aj[lane]      + x1 * aj[lane + 32]
              + e0 * aej[lane]     + e1 * aej[lane + 32];
    float sj1 = x2 * aj[lane + 64] + x3 * aj[lane + 96]
              + e0 * aej[lane + 64]+ e1 * aej[lane + 96];

#pragma unroll
    for (int o = 16; o > 0; o >>= 1) {
        si0 += __shfl_xor_sync(0xffffffffu, si0, o);
        si1 += __shfl_xor_sync(0xffffffffu, si1, o);
        sj0 += __shfl_xor_sync(0xffffffffu, sj0, o);
        sj1 += __shfl_xor_sync(0xffffffffu, sj1, o);
    }
    if (lane == 0) {
        *(float2*)(g_si + 2 * gw) = make_float2(si0, si1);
        *(float2*)(g_sj + 2 * gw) = make_float2(sj0, sj1);
        *(float2*)(g_w  + 2 * gw) = make_float2(0.f, 0.f);
    }
}

// ---------------- Kernel 3: per-edge attention + scatter-add ----------------
// items [0,E) = edges, [E, E+N) = self loops
__global__ void edge_kernel(const int* __restrict__ src, const int* __restrict__ dst,
                            int E, int N)
{
    int i = blockIdx.x * blockDim.x + threadIdx.x;
    if (i >= E + N) return;
    int s, d;
    if (i < E) { s = src[i]; d = dst[i]; }
    else       { s = i - E;  d = s; }

    float2 si = *(const float2*)(g_si + 2 * s);
    float2 sj = *(const float2*)(g_sj + 2 * d);
    float a0 = si.x + sj.x;  a0 = fmaxf(a0, 0.2f * a0);   // leaky relu
    float a1 = si.y + sj.y;  a1 = fmaxf(a1, 0.2f * a1);
    float m  = fmaxf(a0, a1);
    float e0 = __expf(a0 - m);
    float e1 = __expf(a1 - m);
    float inv = __fdividef(1.0f, e0 + e1);

    atomicAdd(g_w + 2 * d,     e0 * inv);   // unused result -> RED.F32
    atomicAdd(g_w + 2 * d + 1, e1 * inv);
}

// ---------------- Kernel 4: out[n,d] = 0.5*(xh[n,0,d]*w0 + xh[n,1,d]*w1) ----
__global__ void out_kernel(float* __restrict__ out, int N)
{
    int i = blockIdx.x * blockDim.x + threadIdx.x;   // over N*16 float4s
    if (i >= N * 16) return;
    int n  = i >> 4;
    int d4 = (i & 15) << 2;
    float2 w = *(const float2*)(g_w + 2 * n);
    float4 a = *(const float4*)(g_xh + (size_t)n * 128 + d4);
    float4 b = *(const float4*)(g_xh + (size_t)n * 128 + 64 + d4);
    float4 o;
    o.x = 0.5f * (a.x * w.x + b.x * w.y);
    o.y = 0.5f * (a.y * w.x + b.y * w.y);
    o.z = 0.5f * (a.z * w.x + b.z * w.y);
    o.w = 0.5f * (a.w * w.x + b.w * w.y);
    ((float4*)out)[i] = o;
}

// ---------------- launcher ---------------------------------------------------
extern "C" void kernel_launch(void* const* d_in, const int* in_sizes, int n_in,
                              void* d_out, int out_size)
{
    const float* x    = (const float*)d_in[0];
    const float* emb  = (const float*)d_in[1];
    const float* W    = (const float*)d_in[2];
    const float* ai   = (const float*)d_in[3];
    const float* aj   = (const float*)d_in[4];
    const float* aei  = (const float*)d_in[5];
    const float* aej  = (const float*)d_in[6];
    const int*   esrc = (const int*)d_in[7];
    const int*   edst = (const int*)d_in[8];
    float* out = (float*)d_out;

    const int N = in_sizes[0] / 128;   // 50000
    const int E = in_sizes[7];         // 1600000

    const size_t smem = (size_t)(128 * 128 + 16 * XS_PITCH) * sizeof(float);
    cudaFuncSetAttribute(gemm_kernel,
                         cudaFuncAttributeMaxDynamicSharedMemorySize, (int)smem);

    gemm_kernel<<<(N + 127) / 128, 256, smem>>>(x, W, N);
    s_kernel  <<<(N + 3) / 4, 128>>>(emb, ai, aj, aei, aej, N);
    edge_kernel<<<(E + N + 255) / 256, 256>>>(esrc, edst, E, N);
    out_kernel<<<(N * 16 + 255) / 256, 256>>>(out, N);
}

// round 3
// speedup vs baseline: 1.0302x; 1.0302x over previous
#include <cuda_runtime.h>
#include <cuda_bf16.h>
#include <cstdint>

// ---------------- scratch (device globals; no allocations allowed) ----------
#define NMAX 50000
__device__ float g_xh[(size_t)NMAX * 128];   // [N, H*D] = [N,128]
__device__ float g_si[NMAX * 2];             // [N, H]
__device__ float g_sj[NMAX * 2];             // [N, H]
__device__ float g_w [NMAX * 2];             // [N, H]

// ---------------- PTX helpers (base sm_103 target: no tcgen05) --------------
__device__ __forceinline__ uint32_t smem_u32(const void* p) {
    uint32_t a;
    asm("{ .reg .u64 t; cvta.to.shared.u64 t, %1; cvt.u32.u64 %0, t; }"
        : "=r"(a) : "l"(p));
    return a;
}
__device__ __forceinline__ void ldsm_x4(uint32_t& r0, uint32_t& r1,
                                        uint32_t& r2, uint32_t& r3, uint32_t addr) {
    asm volatile("ldmatrix.sync.aligned.m8n8.x4.shared.b16 {%0,%1,%2,%3}, [%4];"
                 : "=r"(r0), "=r"(r1), "=r"(r2), "=r"(r3) : "r"(addr));
}
__device__ __forceinline__ void mma16816(float* c, const uint32_t* a, const uint32_t* b) {
    asm volatile(
        "mma.sync.aligned.m16n8k16.row.col.f32.bf16.bf16.f32 "
        "{%0,%1,%2,%3}, {%4,%5,%6,%7}, {%8,%9}, {%0,%1,%2,%3};"
        : "+f"(c[0]), "+f"(c[1]), "+f"(c[2]), "+f"(c[3])
        : "r"(a[0]), "r"(a[1]), "r"(a[2]), "r"(a[3]), "r"(b[0]), "r"(b[1]));
}

__device__ __forceinline__ void split4(float4 v, uint2& hi, uint2& lo) {
    __nv_bfloat16 hx = __float2bfloat16(v.x), hy = __float2bfloat16(v.y);
    __nv_bfloat16 hz = __float2bfloat16(v.z), hw = __float2bfloat16(v.w);
    __nv_bfloat16 lx = __float2bfloat16(v.x - __bfloat162float(hx));
    __nv_bfloat16 ly = __float2bfloat16(v.y - __bfloat162float(hy));
    __nv_bfloat16 lz = __float2bfloat16(v.z - __bfloat162float(hz));
    __nv_bfloat16 lw = __float2bfloat16(v.w - __bfloat162float(hw));
    hi.x = (uint32_t)__bfloat16_as_ushort(hx) | ((uint32_t)__bfloat16_as_ushort(hy) << 16);
    hi.y = (uint32_t)__bfloat16_as_ushort(hz) | ((uint32_t)__bfloat16_as_ushort(hw) << 16);
    lo.x = (uint32_t)__bfloat16_as_ushort(lx) | ((uint32_t)__bfloat16_as_ushort(ly) << 16);
    lo.y = (uint32_t)__bfloat16_as_ushort(lz) | ((uint32_t)__bfloat16_as_ushort(lw) << 16);
}

// ---------------- SMEM layout (bytes) ----------------------------------------
// A,B tiles: 128 rows x pitch 136 bf16 (272B rows -> conflict-free ldmatrix)
#define KP 136
#define O_ATT   0                       // 512 floats = 2048B
#define O_AH    2048
#define O_AL    (O_AH + 34816)
#define O_BH    (O_AL + 34816)
#define O_BL    (O_BH + 34816)
#define SMEM_TOTAL (O_BL + 34816)       // 141312
#define O_STAGE O_AH                    // 128 x 132 floats = 67584B (fits in AH+AL)

// ---------------- Kernel 1: fused GEMM (mma.sync bf16x3) + scores -----------
__global__ __launch_bounds__(256, 1)
void fused_gemm_kernel(const float* __restrict__ x, const float* __restrict__ W,
                       const float* __restrict__ emb,
                       const float* __restrict__ ai,  const float* __restrict__ aj,
                       const float* __restrict__ aei, const float* __restrict__ aej,
                       int N)
{
    extern __shared__ char sm[];
    const uint32_t smb = smem_u32(sm);
    const int tid = threadIdx.x;
    const int wid = tid >> 5;
    const int lid = tid & 31;
    const int row0 = blockIdx.x * 128;

    // ---- stage A = x tile [m][k] (bf16 hi/lo) --------------------------------
#pragma unroll
    for (int i = 0; i < 16; i++) {
        int idx = tid + i * 256;
        int r = idx >> 5, c = (idx & 31) * 4;
        float4 v = make_float4(0.f, 0.f, 0.f, 0.f);
        if (row0 + r < N) v = *(const float4*)(x + (size_t)(row0 + r) * 128 + c);
        uint2 hi, lo;
        split4(v, hi, lo);
        uint32_t off = (uint32_t)(r * KP + c) * 2;
        *(uint2*)(sm + O_AH + off) = hi;
        *(uint2*)(sm + O_AL + off) = lo;
    }
    // ---- stage B = W^T tile [n][k] (bf16 hi/lo) ------------------------------
#pragma unroll
    for (int i = 0; i < 16; i++) {
        int idx = tid + i * 256;
        int n = idx >> 5, k0 = (idx & 31) * 4;
        float4 v;
        v.x = W[(size_t)(k0 + 0) * 128 + n];
        v.y = W[(size_t)(k0 + 1) * 128 + n];
        v.z = W[(size_t)(k0 + 2) * 128 + n];
        v.w = W[(size_t)(k0 + 3) * 128 + n];
        uint2 hi, lo;
        split4(v, hi, lo);
        uint32_t off = (uint32_t)(n * KP + k0) * 2;
        *(uint2*)(sm + O_BH + off) = hi;
        *(uint2*)(sm + O_BL + off) = lo;
    }
    // ---- stage attention vectors ---------------------------------------------
    {
        float* satt = (float*)(sm + O_ATT);
#pragma unroll
        for (int i = 0; i < 2; i++) {
            int t = tid + i * 256;
            float v;
            if      (t < 128) v = ai [t];
            else if (t < 256) v = aj [t - 128];
            else if (t < 384) v = aei[t - 256];
            else              v = aej[t - 384];
            satt[t] = v;
        }
    }
    __syncthreads();

    // ---- MMA main: warp (wid&3) -> 32-row block, (wid>>2) -> 64-col block ----
    const int mrow = (wid & 3) * 32;
    const int ncol = (wid >> 2) * 64;

    float acc[2][8][4];
#pragma unroll
    for (int t = 0; t < 2; t++)
#pragma unroll
        for (int n = 0; n < 8; n++)
#pragma unroll
            for (int k = 0; k < 4; k++) acc[t][n][k] = 0.f;

    // ldmatrix lane addressing (A and B tiles share the same [row][k] form)
    const int l15 = lid & 15;
    const int lh8 = (lid >> 4) * 8;          // A: k-half select
    const int bnt = (lid >> 4) * 8;          // B: n-tile within pair
    const int bkh = ((lid >> 3) & 1) * 8;    // B: k-half select
    const int bnr = lid & 7;                 // B: n-row within tile

    // byte offsets (per lane), k advances by 32B per k-step
    uint32_t aoff = (uint32_t)((mrow + l15) * KP + lh8) * 2;          // + t*16*KP*2 + ks*32
    uint32_t boff = (uint32_t)((ncol + bnt + bnr) * KP + bkh) * 2;    // + p2*16*KP*2 + ks*32

#pragma unroll
    for (int ks = 0; ks < 8; ks++) {
        const uint32_t kb = (uint32_t)ks * 32;
        uint32_t ah[2][4], al[2][4], b[8][2];

        // Ah
#pragma unroll
        for (int t = 0; t < 2; t++)
            ldsm_x4(ah[t][0], ah[t][1], ah[t][2], ah[t][3],
                    smb + O_AH + aoff + (uint32_t)t * (16 * KP * 2) + kb);
        // Bh
#pragma unroll
        for (int p = 0; p < 4; p++)
            ldsm_x4(b[2 * p][0], b[2 * p][1], b[2 * p + 1][0], b[2 * p + 1][1],
                    smb + O_BH + boff + (uint32_t)p * (16 * KP * 2) + kb);
        // HH
#pragma unroll
        for (int t = 0; t < 2; t++)
#pragma unroll
            for (int n = 0; n < 8; n++) mma16816(acc[t][n], ah[t], b[n]);
        // Al
#pragma unroll
        for (int t = 0; t < 2; t++)
            ldsm_x4(al[t][0], al[t][1], al[t][2], al[t][3],
                    smb + O_AL + aoff + (uint32_t)t * (16 * KP * 2) + kb);
        // LH
#pragma unroll
        for (int t = 0; t < 2; t++)
#pragma unroll
            for (int n = 0; n < 8; n++) mma16816(acc[t][n], al[t], b[n]);
        // Bl (overwrite Bh regs)
#pragma unroll
        for (int p = 0; p < 4; p++)
            ldsm_x4(b[2 * p][0], b[2 * p][1], b[2 * p + 1][0], b[2 * p + 1][1],
                    smb + O_BL + boff + (uint32_t)p * (16 * KP * 2) + kb);
        // HL
#pragma unroll
        for (int t = 0; t < 2; t++)
#pragma unroll
            for (int n = 0; n < 8; n++) mma16816(acc[t][n], ah[t], b[n]);
    }

    __syncthreads();   // all ldmatrix done before stage overwrites A tiles

    // ---- epilogue: scores (head q = wid>>2) + stage xh ------------------------
    const int g = lid >> 2, tig = lid & 3, q = wid >> 2;
    float* stage = (float*)(sm + O_STAGE);
    const float* satt = (const float*)(sm + O_ATT);
    const float* attiq = satt + q * 64;
    const float* attjq = satt + 128 + q * 64;
    const float* aeiq  = satt + 256 + q * 64 + tig * 16;
    const float* aejq  = satt + 384 + q * 64 + tig * 16;

    float psi[4], psj[4];
#pragma unroll
    for (int t = 0; t < 2; t++) {
#pragma unroll
        for (int h = 0; h < 2; h++) {
            float si = 0.f, sj = 0.f;
#pragma unroll
            for (int n = 0; n < 8; n++) {
                int c = n * 8 + tig * 2;
                float v0 = acc[t][n][h * 2 + 0];
                float v1 = acc[t][n][h * 2 + 1];
                si += v0 * attiq[c] + v1 * attiq[c + 1];
                sj += v0 * attjq[c] + v1 * attjq[c + 1];
            }
            int grow = row0 + mrow + t * 16 + h * 8 + g;
            if (grow < N) {
                const float4* er = (const float4*)(emb + (size_t)grow * 64 + tig * 16);
#pragma unroll
                for (int e4 = 0; e4 < 4; e4++) {
                    float4 e = er[e4];
                    si += e.x * aeiq[e4 * 4 + 0] + e.y * aeiq[e4 * 4 + 1]
                        + e.z * aeiq[e4 * 4 + 2] + e.w * aeiq[e4 * 4 + 3];
                    sj += e.x * aejq[e4 * 4 + 0] + e.y * aejq[e4 * 4 + 1]
                        + e.z * aejq[e4 * 4 + 2] + e.w * aejq[e4 * 4 + 3];
                }
            }
            psi[t * 2 + h] = si;
            psj[t * 2 + h] = sj;
        }
        // stage this warp's fragment columns
#pragma unroll
        for (int n = 0; n < 8; n++) {
            int r = mrow + t * 16 + g, col = ncol + n * 8 + tig * 2;
            *(float2*)&stage[r * 132 + col]       = make_float2(acc[t][n][0], acc[t][n][1]);
            *(float2*)&stage[(r + 8) * 132 + col] = make_float2(acc[t][n][2], acc[t][n][3]);
        }
    }
    // reduce over the 4-lane tig group
#pragma unroll
    for (int r = 0; r < 4; r++) {
        psi[r] += __shfl_xor_sync(0xffffffffu, psi[r], 1);
        psi[r] += __shfl_xor_sync(0xffffffffu, psi[r], 2);
        psj[r] += __shfl_xor_sync(0xffffffffu, psj[r], 1);
        psj[r] += __shfl_xor_sync(0xffffffffu, psj[r], 2);
    }
    if (tig == 0) {
#pragma unroll
        for (int t = 0; t < 2; t++)
#pragma unroll
            for (int h = 0; h < 2; h++) {
                int grow = row0 + mrow + t * 16 + h * 8 + g;
                if (grow < N) {
                    g_si[2 * grow + q] = psi[t * 2 + h];
                    g_sj[2 * grow + q] = psj[t * 2 + h];
                    if (q == 0) *(float2*)(g_w + 2 * grow) = make_float2(0.f, 0.f);
                }
            }
    }
    __syncthreads();

    // ---- coalesced copy-out of staged xh rows --------------------------------
#pragma unroll
    for (int i = 0; i < 16; i++) {
        int idx = tid + i * 256;
        int r = idx >> 5, c = (idx & 31) * 4;
        if (row0 + r < N)
            *(float4*)(g_xh + (size_t)(row0 + r) * 128 + c) =
                *(const float4*)(stage + r * 132 + c);
    }
}

// ---------------- Kernel 2: per-edge attention + scatter-add ----------------
__global__ void edge_kernel(const int* __restrict__ src, const int* __restrict__ dst,
                            int E, int N)
{
    int i = blockIdx.x * blockDim.x + threadIdx.x;
    if (i >= E + N) return;
    int s, d;
    if (i < E) { s = src[i]; d = dst[i]; }
    else       { s = i - E;  d = s; }

    float2 si = *(const float2*)(g_si + 2 * s);
    float2 sj = *(const float2*)(g_sj + 2 * d);
    float a0 = si.x + sj.x;  a0 = fmaxf(a0, 0.2f * a0);
    float a1 = si.y + sj.y;  a1 = fmaxf(a1, 0.2f * a1);
    float m  = fmaxf(a0, a1);
    float e0 = __expf(a0 - m);
    float e1 = __expf(a1 - m);
    float inv = __fdividef(1.0f, e0 + e1);

    atomicAdd(g_w + 2 * d,     e0 * inv);
    atomicAdd(g_w + 2 * d + 1, e1 * inv);
}

// ---------------- Kernel 3: out[n,d] = 0.5*(xh0*w0 + xh1*w1) ------------------
__global__ void out_kernel(float* __restrict__ out, int N)
{
    int i = blockIdx.x * blockDim.x + threadIdx.x;
    if (i >= N * 16) return;
    int n  = i >> 4;
    int d4 = (i & 15) << 2;
    float2 w = *(const float2*)(g_w + 2 * n);
    float4 a = *(const float4*)(g_xh + (size_t)n * 128 + d4);
    float4 b = *(const float4*)(g_xh + (size_t)n * 128 + 64 + d4);
    float4 o;
    o.x = 0.5f * (a.x * w.x + b.x * w.y);
    o.y = 0.5f * (a.y * w.x + b.y * w.y);
    o.z = 0.5f * (a.z * w.x + b.z * w.y);
    o.w = 0.5f * (a.w * w.x + b.w * w.y);
    ((float4*)out)[i] = o;
}

// ---------------- launcher ---------------------------------------------------
extern "C" void kernel_launch(void* const* d_in, const int* in_sizes, int n_in,
                              void* d_out, int out_size)
{
    const float* x    = (const float*)d_in[0];
    const float* emb  = (const float*)d_in[1];
    const float* W    = (const float*)d_in[2];
    const float* ai   = (const float*)d_in[3];
    const float* aj   = (const float*)d_in[4];
    const float* aei  = (const float*)d_in[5];
    const float* aej  = (const float*)d_in[6];
    const int*   esrc = (const int*)d_in[7];
    const int*   edst = (const int*)d_in[8];
    float* out = (float*)d_out;

    const int N = in_sizes[0] / 128;   // 50000
    const int E = in_sizes[7];         // 1600000

    cudaFuncSetAttribute(fused_gemm_kernel,
                         cudaFuncAttributeMaxDynamicSharedMemorySize, SMEM_TOTAL);

    fused_gemm_kernel<<<(N + 127) / 128, 256, SMEM_TOTAL>>>(x, W, emb, ai, aj, aei, aej, N);
    edge_kernel<<<(E + N + 255) / 256, 256>>>(esrc, edst, E, N);
    out_kernel<<<(N * 16 + 255) / 256, 256>>>(out, N);
}

// round 4
// speedup vs baseline: 1.1310x; 1.0979x over previous
#include <cuda_runtime.h>
#include <cuda_bf16.h>
#include <cstdint>
#include <math.h>

// ---------------- scratch (device globals; no allocations allowed) ----------
#define NMAX 50000
__device__ float  g_xh[(size_t)NMAX * 128];  // [N, H*D] = [N,128]
__device__ float  g_si[NMAX * 2];            // [N, H]
__device__ float  g_sj[NMAX * 2];            // [N, H]
__device__ double g_wd[NMAX];                // packed: deg*2^20 + sum(alpha0)

// ---------------- PTX helpers (base sm_103 target) --------------------------
__device__ __forceinline__ uint32_t smem_u32(const void* p) {
    uint32_t a;
    asm("{ .reg .u64 t; cvta.to.shared.u64 t, %1; cvt.u32.u64 %0, t; }"
        : "=r"(a) : "l"(p));
    return a;
}
__device__ __forceinline__ void ldsm_x4(uint32_t& r0, uint32_t& r1,
                                        uint32_t& r2, uint32_t& r3, uint32_t addr) {
    asm volatile("ldmatrix.sync.aligned.m8n8.x4.shared.b16 {%0,%1,%2,%3}, [%4];"
                 : "=r"(r0), "=r"(r1), "=r"(r2), "=r"(r3) : "r"(addr));
}
__device__ __forceinline__ void mma16816(float* c, const uint32_t* a, const uint32_t* b) {
    asm volatile(
        "mma.sync.aligned.m16n8k16.row.col.f32.bf16.bf16.f32 "
        "{%0,%1,%2,%3}, {%4,%5,%6,%7}, {%8,%9}, {%0,%1,%2,%3};"
        : "+f"(c[0]), "+f"(c[1]), "+f"(c[2]), "+f"(c[3])
        : "r"(a[0]), "r"(a[1]), "r"(a[2]), "r"(a[3]), "r"(b[0]), "r"(b[1]));
}

__device__ __forceinline__ void split4(float4 v, uint2& hi, uint2& lo) {
    __nv_bfloat16 hx = __float2bfloat16(v.x), hy = __float2bfloat16(v.y);
    __nv_bfloat16 hz = __float2bfloat16(v.z), hw = __float2bfloat16(v.w);
    __nv_bfloat16 lx = __float2bfloat16(v.x - __bfloat162float(hx));
    __nv_bfloat16 ly = __float2bfloat16(v.y - __bfloat162float(hy));
    __nv_bfloat16 lz = __float2bfloat16(v.z - __bfloat162float(hz));
    __nv_bfloat16 lw = __float2bfloat16(v.w - __bfloat162float(hw));
    hi.x = (uint32_t)__bfloat16_as_ushort(hx) | ((uint32_t)__bfloat16_as_ushort(hy) << 16);
    hi.y = (uint32_t)__bfloat16_as_ushort(hz) | ((uint32_t)__bfloat16_as_ushort(hw) << 16);
    lo.x = (uint32_t)__bfloat16_as_ushort(lx) | ((uint32_t)__bfloat16_as_ushort(ly) << 16);
    lo.y = (uint32_t)__bfloat16_as_ushort(lz) | ((uint32_t)__bfloat16_as_ushort(lw) << 16);
}

// ---------------- SMEM layout (bytes) ----------------------------------------
#define KP 136                          // bf16 pitch: 272B rows, conflict-free ldmatrix
#define O_ATT   0                       // 512 floats = 2048B
#define O_PSI   2048                    // [2 heads][2 colgroups][128 rows] = 2048B
#define O_PSJ   4096                    // same                              = 2048B
#define O_AH    6144
#define O_AL    (O_AH + 34816)
#define O_BH    (O_AL + 34816)
#define O_BL    (O_BH + 34816)
#define SMEM_TOTAL (O_BL + 34816)       // 145408

// ---------------- Kernel 1: fused GEMM (mma.sync bf16x3) + scores -----------
__global__ __launch_bounds__(512, 1)
void fused_gemm_kernel(const float* __restrict__ x, const float* __restrict__ W,
                       const float* __restrict__ emb,
                       const float* __restrict__ ai,  const float* __restrict__ aj,
                       const float* __restrict__ aei, const float* __restrict__ aej,
                       int N)
{
    extern __shared__ char sm[];
    const uint32_t smb = smem_u32(sm);
    const int tid = threadIdx.x;
    const int wid = tid >> 5;
    const int lid = tid & 31;
    const int row0 = blockIdx.x * 128;

    // ---- stage A = x tile [m][k] (bf16 hi/lo) --------------------------------
#pragma unroll
    for (int i = 0; i < 8; i++) {
        int idx = tid + i * 512;
        int r = idx >> 5, c = (idx & 31) * 4;
        float4 v = make_float4(0.f, 0.f, 0.f, 0.f);
        if (row0 + r < N) v = *(const float4*)(x + (size_t)(row0 + r) * 128 + c);
        uint2 hi, lo;
        split4(v, hi, lo);
        uint32_t off = (uint32_t)(r * KP + c) * 2;
        *(uint2*)(sm + O_AH + off) = hi;
        *(uint2*)(sm + O_AL + off) = lo;
    }
    // ---- stage B = W^T tile [n][k] (bf16 hi/lo) ------------------------------
#pragma unroll
    for (int i = 0; i < 8; i++) {
        int idx = tid + i * 512;
        int n = idx >> 5, k0 = (idx & 31) * 4;
        float4 v;
        v.x = W[(size_t)(k0 + 0) * 128 + n];
        v.y = W[(size_t)(k0 + 1) * 128 + n];
        v.z = W[(size_t)(k0 + 2) * 128 + n];
        v.w = W[(size_t)(k0 + 3) * 128 + n];
        uint2 hi, lo;
        split4(v, hi, lo);
        uint32_t off = (uint32_t)(n * KP + k0) * 2;
        *(uint2*)(sm + O_BH + off) = hi;
        *(uint2*)(sm + O_BL + off) = lo;
    }
    // ---- stage attention vectors ---------------------------------------------
    {
        float* satt = (float*)(sm + O_ATT);
        int t = tid;
        if (t < 512) {
            float v;
            if      (t < 128) v = ai [t];
            else if (t < 256) v = aj [t - 128];
            else if (t < 384) v = aei[t - 256];
            else              v = aej[t - 384];
            satt[t] = v;
        }
    }
    __syncthreads();

    // ---- MMA main: warp grid 4 (rows) x 4 (cols); warp tile 32x32 ------------
    const int mrow = (wid & 3) * 32;
    const int ncol = (wid >> 2) * 32;
    const int q    = ncol >> 6;          // head
    const int cg   = (ncol >> 5) & 1;    // column-group within head

    float acc[2][4][4];
#pragma unroll
    for (int t = 0; t < 2; t++)
#pragma unroll
        for (int n = 0; n < 4; n++)
#pragma unroll
            for (int k = 0; k < 4; k++) acc[t][n][k] = 0.f;

    const int l15 = lid & 15;
    const int lh8 = (lid >> 4) * 8;
    const int bnt = (lid >> 4) * 8;
    const int bkh = ((lid >> 3) & 1) * 8;
    const int bnr = lid & 7;

    uint32_t aoff = (uint32_t)((mrow + l15) * KP + lh8) * 2;
    uint32_t boff = (uint32_t)((ncol + bnt + bnr) * KP + bkh) * 2;

#pragma unroll
    for (int ks = 0; ks < 8; ks++) {
        const uint32_t kb = (uint32_t)ks * 32;
        uint32_t ah[2][4], al[2][4], b[4][2];

#pragma unroll
        for (int t = 0; t < 2; t++)
            ldsm_x4(ah[t][0], ah[t][1], ah[t][2], ah[t][3],
                    smb + O_AH + aoff + (uint32_t)t * (16 * KP * 2) + kb);
#pragma unroll
        for (int p = 0; p < 2; p++)
            ldsm_x4(b[2 * p][0], b[2 * p][1], b[2 * p + 1][0], b[2 * p + 1][1],
                    smb + O_BH + boff + (uint32_t)p * (16 * KP * 2) + kb);
#pragma unroll
        for (int t = 0; t < 2; t++)
#pragma unroll
            for (int n = 0; n < 4; n++) mma16816(acc[t][n], ah[t], b[n]);

#pragma unroll
        for (int t = 0; t < 2; t++)
            ldsm_x4(al[t][0], al[t][1], al[t][2], al[t][3],
                    smb + O_AL + aoff + (uint32_t)t * (16 * KP * 2) + kb);
#pragma unroll
        for (int t = 0; t < 2; t++)
#pragma unroll
            for (int n = 0; n < 4; n++) mma16816(acc[t][n], al[t], b[n]);

#pragma unroll
        for (int p = 0; p < 2; p++)
            ldsm_x4(b[2 * p][0], b[2 * p][1], b[2 * p + 1][0], b[2 * p + 1][1],
                    smb + O_BL + boff + (uint32_t)p * (16 * KP * 2) + kb);
#pragma unroll
        for (int t = 0; t < 2; t++)
#pragma unroll
            for (int n = 0; n < 4; n++) mma16816(acc[t][n], ah[t], b[n]);
    }

    // ---- direct coalesced-sector writeout of xh fragments --------------------
    const int g = lid >> 2, tig = lid & 3;
#pragma unroll
    for (int t = 0; t < 2; t++)
#pragma unroll
        for (int n = 0; n < 4; n++) {
            int r = row0 + mrow + t * 16 + g;
            int c = ncol + n * 8 + tig * 2;
            if (r < N)
                *(float2*)(g_xh + (size_t)r * 128 + c) = make_float2(acc[t][n][0], acc[t][n][1]);
            if (r + 8 < N)
                *(float2*)(g_xh + (size_t)(r + 8) * 128 + c) = make_float2(acc[t][n][2], acc[t][n][3]);
        }

    // ---- partial scores for this warp's 32 columns ----------------------------
    const float* satt = (const float*)(sm + O_ATT);
    const float* attiq = satt + q * 64 + cg * 32;
    const float* attjq = satt + 128 + q * 64 + cg * 32;
    const float* aeiq  = satt + 256 + q * 64 + tig * 16;
    const float* aejq  = satt + 384 + q * 64 + tig * 16;

    float* psiA = (float*)(sm + O_PSI);   // [q][cg][row]
    float* psjA = (float*)(sm + O_PSJ);

    float psi[4], psj[4];
#pragma unroll
    for (int t = 0; t < 2; t++)
#pragma unroll
        for (int h = 0; h < 2; h++) {
            float si = 0.f, sj = 0.f;
#pragma unroll
            for (int n = 0; n < 4; n++) {
                int c = n * 8 + tig * 2;
                float v0 = acc[t][n][h * 2 + 0];
                float v1 = acc[t][n][h * 2 + 1];
                si += v0 * attiq[c] + v1 * attiq[c + 1];
                sj += v0 * attjq[c] + v1 * attjq[c + 1];
            }
            if (cg == 0) {  // add embedding term exactly once per (row, head)
                int grow = row0 + mrow + t * 16 + h * 8 + g;
                if (grow < N) {
                    const float4* er = (const float4*)(emb + (size_t)grow * 64 + tig * 16);
#pragma unroll
                    for (int e4 = 0; e4 < 4; e4++) {
                        float4 e = er[e4];
                        si += e.x * aeiq[e4 * 4 + 0] + e.y * aeiq[e4 * 4 + 1]
                            + e.z * aeiq[e4 * 4 + 2] + e.w * aeiq[e4 * 4 + 3];
                        sj += e.x * aejq[e4 * 4 + 0] + e.y * aejq[e4 * 4 + 1]
                            + e.z * aejq[e4 * 4 + 2] + e.w * aejq[e4 * 4 + 3];
                    }
                }
            }
            psi[t * 2 + h] = si;
            psj[t * 2 + h] = sj;
        }
#pragma unroll
    for (int r = 0; r < 4; r++) {
        psi[r] += __shfl_xor_sync(0xffffffffu, psi[r], 1);
        psi[r] += __shfl_xor_sync(0xffffffffu, psi[r], 2);
        psj[r] += __shfl_xor_sync(0xffffffffu, psj[r], 1);
        psj[r] += __shfl_xor_sync(0xffffffffu, psj[r], 2);
    }
    if (tig == 0) {
#pragma unroll
        for (int t = 0; t < 2; t++)
#pragma unroll
            for (int h = 0; h < 2; h++) {
                int lrow = mrow + t * 16 + h * 8 + g;
                psiA[(q * 2 + cg) * 128 + lrow] = psi[t * 2 + h];
                psjA[(q * 2 + cg) * 128 + lrow] = psj[t * 2 + h];
            }
    }
    __syncthreads();

    // ---- combine partials, emit scores + zero packed accumulator -------------
    if (tid < 128) {
        int grow = row0 + tid;
        if (grow < N) {
            float si0 = psiA[tid]       + psiA[128 + tid];
            float si1 = psiA[256 + tid] + psiA[384 + tid];
            float sj0 = psjA[tid]       + psjA[128 + tid];
            float sj1 = psjA[256 + tid] + psjA[384 + tid];
            *(float2*)(g_si + 2 * grow) = make_float2(si0, si1);
            *(float2*)(g_sj + 2 * grow) = make_float2(sj0, sj1);
            g_wd[grow] = 0.0;
        }
    }
}

// ---------------- Kernel 2: per-edge attention, ONE packed double atomic -----
__global__ void edge_kernel(const int* __restrict__ src, const int* __restrict__ dst,
                            int E, int N)
{
    int i = blockIdx.x * blockDim.x + threadIdx.x;
    if (i >= E + N) return;
    int s, d;
    if (i < E) { s = src[i]; d = dst[i]; }
    else       { s = i - E;  d = s; }

    float2 si = *(const float2*)(g_si + 2 * s);
    float2 sj = *(const float2*)(g_sj + 2 * d);
    float a0 = si.x + sj.x;  a0 = fmaxf(a0, 0.2f * a0);
    float a1 = si.y + sj.y;  a1 = fmaxf(a1, 0.2f * a1);
    float m  = fmaxf(a0, a1);
    float e0 = __expf(a0 - m);
    float e1 = __expf(a1 - m);
    float alpha0 = __fdividef(e0, e0 + e1);     // alpha1 = 1 - alpha0

    atomicAdd(g_wd + d, (double)alpha0 + 1048576.0);   // low: sum(alpha0), high: degree
}

// ---------------- Kernel 3: out[n,d] = 0.5*(xh0*w0 + xh1*w1) ------------------
__global__ void out_kernel(float* __restrict__ out, int N)
{
    int i = blockIdx.x * blockDim.x + threadIdx.x;
    if (i >= N * 16) return;
    int n  = i >> 4;
    int d4 = (i & 15) << 2;
    double v   = g_wd[n];
    double deg = floor(v * 9.5367431640625e-07);       // v / 2^20
    float  w0  = (float)(v - deg * 1048576.0);
    float  w1  = (float)deg - w0;
    float4 a = *(const float4*)(g_xh + (size_t)n * 128 + d4);
    float4 b = *(const float4*)(g_xh + (size_t)n * 128 + 64 + d4);
    float4 o;
    o.x = 0.5f * (a.x * w0 + b.x * w1);
    o.y = 0.5f * (a.y * w0 + b.y * w1);
    o.z = 0.5f * (a.z * w0 + b.z * w1);
    o.w = 0.5f * (a.w * w0 + b.w * w1);
    ((float4*)out)[i] = o;
}

// ---------------- launcher ---------------------------------------------------
extern "C" void kernel_launch(void* const* d_in, const int* in_sizes, int n_in,
                              void* d_out, int out_size)
{
    const float* x    = (const float*)d_in[0];
    const float* emb  = (const float*)d_in[1];
    const float* W    = (const float*)d_in[2];
    const float* ai   = (const float*)d_in[3];
    const float* aj   = (const float*)d_in[4];
    const float* aei  = (const float*)d_in[5];
    const float* aej  = (const float*)d_in[6];
    const int*   esrc = (const int*)d_in[7];
    const int*   edst = (const int*)d_in[8];
    float* out = (float*)d_out;

    const int N = in_sizes[0] / 128;   // 50000
    const int E = in_sizes[7];         // 1600000

    cudaFuncSetAttribute(fused_gemm_kernel,
                         cudaFuncAttributeMaxDynamicSharedMemorySize, SMEM_TOTAL);

    fused_gemm_kernel<<<(N + 127) / 128, 512, SMEM_TOTAL>>>(x, W, emb, ai, aj, aei, aej, N);
    edge_kernel<<<(E + N + 255) / 256, 256>>>(esrc, edst, E, N);
    out_kernel<<<(N * 16 + 255) / 256, 256>>>(out, N);
}

// round 5
// speedup vs baseline: 1.3102x; 1.1584x over previous
#include <cuda_runtime.h>
#include <cuda_bf16.h>
#include <cstdint>
#include <math.h>

// ---------------- scratch (device globals; no allocations allowed) ----------
#define NMAX 50000
__device__ float  g_xh[(size_t)NMAX * 128];  // [N, H*D] = [N,128]
__device__ float  g_si[NMAX * 2];            // [N, H]
__device__ float  g_sj[NMAX * 2];            // [N, H]
__device__ double g_wd[NMAX];                // packed: deg*2^20 + sum(alpha0)

// ---------------- PTX helpers (base sm_103 target) --------------------------
__device__ __forceinline__ uint32_t smem_u32(const void* p) {
    uint32_t a;
    asm("{ .reg .u64 t; cvta.to.shared.u64 t, %1; cvt.u32.u64 %0, t; }"
        : "=r"(a) : "l"(p));
    return a;
}
__device__ __forceinline__ void ldsm_x4(uint32_t& r0, uint32_t& r1,
                                        uint32_t& r2, uint32_t& r3, uint32_t addr) {
    asm volatile("ldmatrix.sync.aligned.m8n8.x4.shared.b16 {%0,%1,%2,%3}, [%4];"
                 : "=r"(r0), "=r"(r1), "=r"(r2), "=r"(r3) : "r"(addr));
}
__device__ __forceinline__ void ldsm_x4t(uint32_t& r0, uint32_t& r1,
                                         uint32_t& r2, uint32_t& r3, uint32_t addr) {
    asm volatile("ldmatrix.sync.aligned.m8n8.x4.trans.shared.b16 {%0,%1,%2,%3}, [%4];"
                 : "=r"(r0), "=r"(r1), "=r"(r2), "=r"(r3) : "r"(addr));
}
__device__ __forceinline__ void mma16816(float* c, const uint32_t* a, const uint32_t* b) {
    asm volatile(
        "mma.sync.aligned.m16n8k16.row.col.f32.bf16.bf16.f32 "
        "{%0,%1,%2,%3}, {%4,%5,%6,%7}, {%8,%9}, {%0,%1,%2,%3};"
        : "+f"(c[0]), "+f"(c[1]), "+f"(c[2]), "+f"(c[3])
        : "r"(a[0]), "r"(a[1]), "r"(a[2]), "r"(a[3]), "r"(b[0]), "r"(b[1]));
}

__device__ __forceinline__ void split4(float4 v, uint2& hi, uint2& lo) {
    __nv_bfloat16 hx = __float2bfloat16(v.x), hy = __float2bfloat16(v.y);
    __nv_bfloat16 hz = __float2bfloat16(v.z), hw = __float2bfloat16(v.w);
    __nv_bfloat16 lx = __float2bfloat16(v.x - __bfloat162float(hx));
    __nv_bfloat16 ly = __float2bfloat16(v.y - __bfloat162float(hy));
    __nv_bfloat16 lz = __float2bfloat16(v.z - __bfloat162float(hz));
    __nv_bfloat16 lw = __float2bfloat16(v.w - __bfloat162float(hw));
    hi.x = (uint32_t)__bfloat16_as_ushort(hx) | ((uint32_t)__bfloat16_as_ushort(hy) << 16);
    hi.y = (uint32_t)__bfloat16_as_ushort(hz) | ((uint32_t)__bfloat16_as_ushort(hw) << 16);
    lo.x = (uint32_t)__bfloat16_as_ushort(lx) | ((uint32_t)__bfloat16_as_ushort(ly) << 16);
    lo.y = (uint32_t)__bfloat16_as_ushort(lz) | ((uint32_t)__bfloat16_as_ushort(lw) << 16);
}

// ---------------- SMEM layout (bytes) ----------------------------------------
// pitch 136 bf16 = 272B rows: 272 mod 128 = 16 -> conflict-free ldmatrix (both modes)
#define KP 136
#define O_ATT   0                       // 512 floats = 2048B
#define O_PSI   2048                    // [2 heads][2 colgroups][64 rows] = 1024B
#define O_PSJ   3072                    // 1024B
#define O_AH    4096                    // A hi  [64 m][KP k]  = 17408B
#define O_AL    (O_AH + 17408)          // A lo
#define O_BH    (O_AL + 17408)          // B hi  [128 k][KP n] = 34816B (natural W layout)
#define O_BL    (O_BH + 34816)          // B lo
#define SMEM_TOTAL (O_BL + 34816)       // 108544 -> 2 CTAs/SM

// ---------------- Kernel 1: fused GEMM (mma.sync bf16x3) + scores -----------
// 64-row tile, 256 threads, warp grid: (wid&1) row-group x (wid>>1) col-group
__global__ __launch_bounds__(256, 2)
void fused_gemm_kernel(const float* __restrict__ x, const float* __restrict__ W,
                       const float* __restrict__ emb,
                       const float* __restrict__ ai,  const float* __restrict__ aj,
                       const float* __restrict__ aei, const float* __restrict__ aej,
                       int N)
{
    extern __shared__ char sm[];
    const uint32_t smb = smem_u32(sm);
    const int tid = threadIdx.x;
    const int wid = tid >> 5;
    const int lid = tid & 31;
    const int row0 = blockIdx.x * 64;

    // ---- stage A = x tile [m][k] (bf16 hi/lo), coalesced ---------------------
#pragma unroll
    for (int i = 0; i < 8; i++) {
        int idx = tid + i * 256;
        int r = idx >> 5, c = (idx & 31) * 4;
        float4 v = make_float4(0.f, 0.f, 0.f, 0.f);
        if (row0 + r < N) v = *(const float4*)(x + (size_t)(row0 + r) * 128 + c);
        uint2 hi, lo;
        split4(v, hi, lo);
        uint32_t off = (uint32_t)(r * KP + c) * 2;
        *(uint2*)(sm + O_AH + off) = hi;
        *(uint2*)(sm + O_AL + off) = lo;
    }
    // ---- stage B = W in NATURAL [k][n] layout (bf16 hi/lo), coalesced --------
#pragma unroll
    for (int i = 0; i < 16; i++) {
        int idx = tid + i * 256;
        int k = idx >> 5, n = (idx & 31) * 4;
        float4 v = *(const float4*)(W + (size_t)k * 128 + n);
        uint2 hi, lo;
        split4(v, hi, lo);
        uint32_t off = (uint32_t)(k * KP + n) * 2;
        *(uint2*)(sm + O_BH + off) = hi;
        *(uint2*)(sm + O_BL + off) = lo;
    }
    // ---- stage attention vectors ---------------------------------------------
    {
        float* satt = (float*)(sm + O_ATT);
#pragma unroll
        for (int i = 0; i < 2; i++) {
            int t = tid + i * 256;
            float v;
            if      (t < 128) v = ai [t];
            else if (t < 256) v = aj [t - 128];
            else if (t < 384) v = aei[t - 256];
            else              v = aej[t - 384];
            satt[t] = v;
        }
    }
    __syncthreads();

    // ---- MMA main: warp tile 32x32 --------------------------------------------
    const int mrow = (wid & 1) * 32;
    const int ncol = (wid >> 1) * 32;
    const int q    = ncol >> 6;          // head
    const int cg   = (ncol >> 5) & 1;    // column-group within head

    float acc[2][4][4];
#pragma unroll
    for (int t = 0; t < 2; t++)
#pragma unroll
        for (int n = 0; n < 4; n++)
#pragma unroll
            for (int k = 0; k < 4; k++) acc[t][n][k] = 0.f;

    // A (non-trans) lane addressing in [m][k]
    const int l15 = lid & 15;
    const int lh8 = (lid >> 4) * 8;
    uint32_t aoff = (uint32_t)((mrow + l15) * KP + lh8) * 2;

    // B (trans) lane addressing in [k][n]: row = khalf*8 + (lid&7), col = nblk
    const int bkr = ((lid >> 3) & 1) * 8 + (lid & 7);   // k row within 16
    const int bnc = (lid >> 4) * 8;                     // n sub-block
    uint32_t boff = (uint32_t)(bkr * KP + ncol + bnc) * 2;

#pragma unroll
    for (int ks = 0; ks < 8; ks++) {
        const uint32_t akb = (uint32_t)ks * 32;             // 16 bf16 in k
        const uint32_t bkb = (uint32_t)ks * (16 * KP * 2);  // 16 k-rows
        uint32_t ah[2][4], al[2][4], b[4][2];

#pragma unroll
        for (int t = 0; t < 2; t++)
            ldsm_x4(ah[t][0], ah[t][1], ah[t][2], ah[t][3],
                    smb + O_AH + aoff + (uint32_t)t * (16 * KP * 2) + akb);
#pragma unroll
        for (int p = 0; p < 2; p++)
            ldsm_x4t(b[2 * p][0], b[2 * p][1], b[2 * p + 1][0], b[2 * p + 1][1],
                     smb + O_BH + boff + bkb + (uint32_t)p * 32);
#pragma unroll
        for (int t = 0; t < 2; t++)
#pragma unroll
            for (int n = 0; n < 4; n++) mma16816(acc[t][n], ah[t], b[n]);

#pragma unroll
        for (int t = 0; t < 2; t++)
            ldsm_x4(al[t][0], al[t][1], al[t][2], al[t][3],
                    smb + O_AL + aoff + (uint32_t)t * (16 * KP * 2) + akb);
#pragma unroll
        for (int t = 0; t < 2; t++)
#pragma unroll
            for (int n = 0; n < 4; n++) mma16816(acc[t][n], al[t], b[n]);

#pragma unroll
        for (int p = 0; p < 2; p++)
            ldsm_x4t(b[2 * p][0], b[2 * p][1], b[2 * p + 1][0], b[2 * p + 1][1],
                     smb + O_BL + boff + bkb + (uint32_t)p * 32);
#pragma unroll
        for (int t = 0; t < 2; t++)
#pragma unroll
            for (int n = 0; n < 4; n++) mma16816(acc[t][n], ah[t], b[n]);
    }

    // ---- direct coalesced-sector writeout of xh fragments --------------------
    const int g = lid >> 2, tig = lid & 3;
#pragma unroll
    for (int t = 0; t < 2; t++)
#pragma unroll
        for (int n = 0; n < 4; n++) {
            int r = row0 + mrow + t * 16 + g;
            int c = ncol + n * 8 + tig * 2;
            if (r < N)
                *(float2*)(g_xh + (size_t)r * 128 + c) = make_float2(acc[t][n][0], acc[t][n][1]);
            if (r + 8 < N)
                *(float2*)(g_xh + (size_t)(r + 8) * 128 + c) = make_float2(acc[t][n][2], acc[t][n][3]);
        }

    // ---- partial scores for this warp's 32 columns ----------------------------
    const float* satt = (const float*)(sm + O_ATT);
    const float* attiq = satt + q * 64 + cg * 32;
    const float* attjq = satt + 128 + q * 64 + cg * 32;
    const float* aeiq  = satt + 256 + q * 64 + tig * 16;
    const float* aejq  = satt + 384 + q * 64 + tig * 16;

    float* psiA = (float*)(sm + O_PSI);   // [q*2+cg][64 rows]
    float* psjA = (float*)(sm + O_PSJ);

    float psi[4], psj[4];
#pragma unroll
    for (int t = 0; t < 2; t++)
#pragma unroll
        for (int h = 0; h < 2; h++) {
            float si = 0.f, sj = 0.f;
#pragma unroll
            for (int n = 0; n < 4; n++) {
                int c = n * 8 + tig * 2;
                float v0 = acc[t][n][h * 2 + 0];
                float v1 = acc[t][n][h * 2 + 1];
                si += v0 * attiq[c] + v1 * attiq[c + 1];
                sj += v0 * attjq[c] + v1 * attjq[c + 1];
            }
            if (cg == 0) {  // add embedding term exactly once per (row, head)
                int grow = row0 + mrow + t * 16 + h * 8 + g;
                if (grow < N) {
                    const float4* er = (const float4*)(emb + (size_t)grow * 64 + tig * 16);
#pragma unroll
                    for (int e4 = 0; e4 < 4; e4++) {
                        float4 e = er[e4];
                        si += e.x * aeiq[e4 * 4 + 0] + e.y * aeiq[e4 * 4 + 1]
                            + e.z * aeiq[e4 * 4 + 2] + e.w * aeiq[e4 * 4 + 3];
                        sj += e.x * aejq[e4 * 4 + 0] + e.y * aejq[e4 * 4 + 1]
                            + e.z * aejq[e4 * 4 + 2] + e.w * aejq[e4 * 4 + 3];
                    }
                }
            }
            psi[t * 2 + h] = si;
            psj[t * 2 + h] = sj;
        }
#pragma unroll
    for (int r = 0; r < 4; r++) {
        psi[r] += __shfl_xor_sync(0xffffffffu, psi[r], 1);
        psi[r] += __shfl_xor_sync(0xffffffffu, psi[r], 2);
        psj[r] += __shfl_xor_sync(0xffffffffu, psj[r], 1);
        psj[r] += __shfl_xor_sync(0xffffffffu, psj[r], 2);
    }
    if (tig == 0) {
#pragma unroll
        for (int t = 0; t < 2; t++)
#pragma unroll
            for (int h = 0; h < 2; h++) {
                int lrow = mrow + t * 16 + h * 8 + g;
                psiA[(q * 2 + cg) * 64 + lrow] = psi[t * 2 + h];
                psjA[(q * 2 + cg) * 64 + lrow] = psj[t * 2 + h];
            }
    }
    __syncthreads();

    // ---- combine partials, emit scores + zero packed accumulator -------------
    if (tid < 64) {
        int grow = row0 + tid;
        if (grow < N) {
            float si0 = psiA[tid]       + psiA[64 + tid];
            float si1 = psiA[128 + tid] + psiA[192 + tid];
            float sj0 = psjA[tid]       + psjA[64 + tid];
            float sj1 = psjA[128 + tid] + psjA[192 + tid];
            *(float2*)(g_si + 2 * grow) = make_float2(si0, si1);
            *(float2*)(g_sj + 2 * grow) = make_float2(sj0, sj1);
            g_wd[grow] = 0.0;
        }
    }
}

// ---------------- Kernel 2: per-edge attention, ONE packed double atomic -----
__global__ void edge_kernel(const int* __restrict__ src, const int* __restrict__ dst,
                            int E, int N)
{
    int i = blockIdx.x * blockDim.x + threadIdx.x;
    if (i >= E + N) return;
    int s, d;
    if (i < E) { s = src[i]; d = dst[i]; }
    else       { s = i - E;  d = s; }

    float2 si = *(const float2*)(g_si + 2 * s);
    float2 sj = *(const float2*)(g_sj + 2 * d);
    float a0 = si.x + sj.x;  a0 = fmaxf(a0, 0.2f * a0);
    float a1 = si.y + sj.y;  a1 = fmaxf(a1, 0.2f * a1);
    float m  = fmaxf(a0, a1);
    float e0 = __expf(a0 - m);
    float e1 = __expf(a1 - m);
    float alpha0 = __fdividef(e0, e0 + e1);     // alpha1 = 1 - alpha0

    atomicAdd(g_wd + d, (double)alpha0 + 1048576.0);   // low: sum(alpha0), high: degree
}

// ---------------- Kernel 3: out[n,d] = 0.5*(xh0*w0 + xh1*w1) ------------------
__global__ void out_kernel(float* __restrict__ out, int N)
{
    int i = blockIdx.x * blockDim.x + threadIdx.x;
    if (i >= N * 16) return;
    int n  = i >> 4;
    int d4 = (i & 15) << 2;
    double v   = g_wd[n];
    double deg = floor(v * 9.5367431640625e-07);       // v / 2^20
    float  w0  = (float)(v - deg * 1048576.0);
    float  w1  = (float)deg - w0;
    float4 a = *(const float4*)(g_xh + (size_t)n * 128 + d4);
    float4 b = *(const float4*)(g_xh + (size_t)n * 128 + 64 + d4);
    float4 o;
    o.x = 0.5f * (a.x * w0 + b.x * w1);
    o.y = 0.5f * (a.y * w0 + b.y * w1);
    o.z = 0.5f * (a.z * w0 + b.z * w1);
    o.w = 0.5f * (a.w * w0 + b.w * w1);
    ((float4*)out)[i] = o;
}

// ---------------- launcher ---------------------------------------------------
extern "C" void kernel_launch(void* const* d_in, const int* in_sizes, int n_in,
                              void* d_out, int out_size)
{
    const float* x    = (const float*)d_in[0];
    const float* emb  = (const float*)d_in[1];
    const float* W    = (const float*)d_in[2];
    const float* ai   = (const float*)d_in[3];
    const float* aj   = (const float*)d_in[4];
    const float* aei  = (const float*)d_in[5];
    const float* aej  = (const float*)d_in[6];
    const int*   esrc = (const int*)d_in[7];
    const int*   edst = (const int*)d_in[8];
    float* out = (float*)d_out;

    const int N = in_sizes[0] / 128;   // 50000
    const int E = in_sizes[7];         // 1600000

    cudaFuncSetAttribute(fused_gemm_kernel,
                         cudaFuncAttributeMaxDynamicSharedMemorySize, SMEM_TOTAL);

    fused_gemm_kernel<<<(N + 63) / 64, 256, SMEM_TOTAL>>>(x, W, emb, ai, aj, aei, aej, N);
    edge_kernel<<<(E + N + 255) / 256, 256>>>(esrc, edst, E, N);
    out_kernel<<<(N * 16 + 255) / 256, 256>>>(out, N);
}

// round 6
// speedup vs baseline: 1.5793x; 1.2053x over previous
#include <cuda_runtime.h>
#include <cuda_bf16.h>
#include <cstdint>
#include <math.h>

// ---------------- scratch (device globals; no allocations allowed) ----------
#define NMAX 50000
__device__ float  g_xh[(size_t)NMAX * 128];  // [N, H*D] = [N,128]
__device__ float  g_si[NMAX * 2];            // [N, H]
__device__ float  g_sj[NMAX * 2];            // [N, H]
__device__ double g_wd[NMAX];                // packed: deg*2^20 + sum(alpha0)
__device__ __nv_bfloat16 g_wh[128 * 128];    // W hi, natural [k][n]
__device__ __nv_bfloat16 g_wl[128 * 128];    // W lo

// ---------------- PTX helpers (base sm_103 target) --------------------------
__device__ __forceinline__ uint32_t smem_u32(const void* p) {
    uint32_t a;
    asm("{ .reg .u64 t; cvta.to.shared.u64 t, %1; cvt.u32.u64 %0, t; }"
        : "=r"(a) : "l"(p));
    return a;
}
__device__ __forceinline__ void ldsm_x4(uint32_t& r0, uint32_t& r1,
                                        uint32_t& r2, uint32_t& r3, uint32_t addr) {
    asm volatile("ldmatrix.sync.aligned.m8n8.x4.shared.b16 {%0,%1,%2,%3}, [%4];"
                 : "=r"(r0), "=r"(r1), "=r"(r2), "=r"(r3) : "r"(addr));
}
__device__ __forceinline__ void ldsm_x4t(uint32_t& r0, uint32_t& r1,
                                         uint32_t& r2, uint32_t& r3, uint32_t addr) {
    asm volatile("ldmatrix.sync.aligned.m8n8.x4.trans.shared.b16 {%0,%1,%2,%3}, [%4];"
                 : "=r"(r0), "=r"(r1), "=r"(r2), "=r"(r3) : "r"(addr));
}
__device__ __forceinline__ void mma16816(float* c, const uint32_t* a, const uint32_t* b) {
    asm volatile(
        "mma.sync.aligned.m16n8k16.row.col.f32.bf16.bf16.f32 "
        "{%0,%1,%2,%3}, {%4,%5,%6,%7}, {%8,%9}, {%0,%1,%2,%3};"
        : "+f"(c[0]), "+f"(c[1]), "+f"(c[2]), "+f"(c[3])
        : "r"(a[0]), "r"(a[1]), "r"(a[2]), "r"(a[3]), "r"(b[0]), "r"(b[1]));
}

__device__ __forceinline__ void split4(float4 v, uint2& hi, uint2& lo) {
    __nv_bfloat16 hx = __float2bfloat16(v.x), hy = __float2bfloat16(v.y);
    __nv_bfloat16 hz = __float2bfloat16(v.z), hw = __float2bfloat16(v.w);
    __nv_bfloat16 lx = __float2bfloat16(v.x - __bfloat162float(hx));
    __nv_bfloat16 ly = __float2bfloat16(v.y - __bfloat162float(hy));
    __nv_bfloat16 lz = __float2bfloat16(v.z - __bfloat162float(hz));
    __nv_bfloat16 lw = __float2bfloat16(v.w - __bfloat162float(hw));
    hi.x = (uint32_t)__bfloat16_as_ushort(hx) | ((uint32_t)__bfloat16_as_ushort(hy) << 16);
    hi.y = (uint32_t)__bfloat16_as_ushort(hz) | ((uint32_t)__bfloat16_as_ushort(hw) << 16);
    lo.x = (uint32_t)__bfloat16_as_ushort(lx) | ((uint32_t)__bfloat16_as_ushort(ly) << 16);
    lo.y = (uint32_t)__bfloat16_as_ushort(lz) | ((uint32_t)__bfloat16_as_ushort(lw) << 16);
}

// ---------------- SMEM layout (bytes) ----------------------------------------
#define KP 136
#define O_ATT   0                       // 512 floats = 2048B
#define O_PSI   2048                    // 1024B
#define O_PSJ   3072                    // 1024B
#define O_AH    4096                    // A hi  [64 m][KP k]  = 17408B
#define O_AL    (O_AH + 17408)
#define O_BH    (O_AL + 17408)          // B hi  [128 k][KP n] = 34816B
#define O_BL    (O_BH + 34816)
#define SMEM_TOTAL (O_BL + 34816)       // 108544 -> 2 CTAs/SM

// ---------------- Kernel 0: precompute W bf16 hi/lo split --------------------
__global__ void wsplit_kernel(const float* __restrict__ W)
{
    int i = blockIdx.x * blockDim.x + threadIdx.x;   // over 4096 float4s
    if (i >= 128 * 128 / 4) return;
    float4 v = ((const float4*)W)[i];
    uint2 hi, lo;
    split4(v, hi, lo);
    ((uint2*)g_wh)[i] = hi;
    ((uint2*)g_wl)[i] = lo;
}

// ---------------- Kernel 1: persistent fused GEMM + scores -------------------
__global__ __launch_bounds__(256, 2)
void fused_gemm_kernel(const float* __restrict__ x,
                       const float* __restrict__ emb,
                       const float* __restrict__ ai,  const float* __restrict__ aj,
                       const float* __restrict__ aei, const float* __restrict__ aej,
                       int N, int ntiles)
{
    extern __shared__ char sm[];
    const uint32_t smb = smem_u32(sm);
    const int tid = threadIdx.x;
    const int wid = tid >> 5;
    const int lid = tid & 31;

    // ---- stage B ONCE: pure copy of precomputed split (uint4 = 8 bf16) -------
#pragma unroll
    for (int i = 0; i < 8; i++) {
        int idx = tid + i * 256;            // over 2048 uint4s
        int k = idx >> 4, n = (idx & 15) * 8;
        uint32_t off = (uint32_t)(k * KP + n) * 2;
        *(uint4*)(sm + O_BH + off) = ((const uint4*)g_wh)[idx];
        *(uint4*)(sm + O_BL + off) = ((const uint4*)g_wl)[idx];
    }
    // ---- stage attention vectors ---------------------------------------------
    {
        float* satt = (float*)(sm + O_ATT);
#pragma unroll
        for (int i = 0; i < 2; i++) {
            int t = tid + i * 256;
            float v;
            if      (t < 128) v = ai [t];
            else if (t < 256) v = aj [t - 128];
            else if (t < 384) v = aei[t - 256];
            else              v = aej[t - 384];
            satt[t] = v;
        }
    }

    // warp tile coords (constant across tiles)
    const int mrow = (wid & 1) * 32;
    const int ncol = (wid >> 1) * 32;
    const int q    = ncol >> 6;
    const int cg   = (ncol >> 5) & 1;
    const int g    = lid >> 2, tig = lid & 3;

    const int l15 = lid & 15;
    const int lh8 = (lid >> 4) * 8;
    const uint32_t aoff = (uint32_t)((mrow + l15) * KP + lh8) * 2;
    const int bkr = ((lid >> 3) & 1) * 8 + (lid & 7);
    const int bnc = (lid >> 4) * 8;
    const uint32_t boff = (uint32_t)(bkr * KP + ncol + bnc) * 2;

    const float* satt = (const float*)(sm + O_ATT);
    const float* attiq = satt + q * 64 + cg * 32;
    const float* attjq = satt + 128 + q * 64 + cg * 32;
    const float* aeiq  = satt + 256 + q * 64 + tig * 16;
    const float* aejq  = satt + 384 + q * 64 + tig * 16;
    float* psiA = (float*)(sm + O_PSI);
    float* psjA = (float*)(sm + O_PSJ);

    for (int tile = blockIdx.x; tile < ntiles; tile += gridDim.x) {
        const int row0 = tile * 64;

        // ---- stage A tile (bf16 hi/lo split) ----------------------------------
#pragma unroll
        for (int i = 0; i < 8; i++) {
            int idx = tid + i * 256;
            int r = idx >> 5, c = (idx & 31) * 4;
            float4 v = make_float4(0.f, 0.f, 0.f, 0.f);
            if (row0 + r < N) v = *(const float4*)(x + (size_t)(row0 + r) * 128 + c);
            uint2 hi, lo;
            split4(v, hi, lo);
            uint32_t off = (uint32_t)(r * KP + c) * 2;
            *(uint2*)(sm + O_AH + off) = hi;
            *(uint2*)(sm + O_AL + off) = lo;
        }
        __syncthreads();

        // ---- MMA ----------------------------------------------------------------
        float acc[2][4][4];
#pragma unroll
        for (int t = 0; t < 2; t++)
#pragma unroll
            for (int n = 0; n < 4; n++)
#pragma unroll
                for (int k = 0; k < 4; k++) acc[t][n][k] = 0.f;

#pragma unroll
        for (int ks = 0; ks < 8; ks++) {
            const uint32_t akb = (uint32_t)ks * 32;
            const uint32_t bkb = (uint32_t)ks * (16 * KP * 2);
            uint32_t ah[2][4], al[2][4], b[4][2];

#pragma unroll
            for (int t = 0; t < 2; t++)
                ldsm_x4(ah[t][0], ah[t][1], ah[t][2], ah[t][3],
                        smb + O_AH + aoff + (uint32_t)t * (16 * KP * 2) + akb);
#pragma unroll
            for (int p = 0; p < 2; p++)
                ldsm_x4t(b[2 * p][0], b[2 * p][1], b[2 * p + 1][0], b[2 * p + 1][1],
                         smb + O_BH + boff + bkb + (uint32_t)p * 32);
#pragma unroll
            for (int t = 0; t < 2; t++)
#pragma unroll
                for (int n = 0; n < 4; n++) mma16816(acc[t][n], ah[t], b[n]);

#pragma unroll
            for (int t = 0; t < 2; t++)
                ldsm_x4(al[t][0], al[t][1], al[t][2], al[t][3],
                        smb + O_AL + aoff + (uint32_t)t * (16 * KP * 2) + akb);
#pragma unroll
            for (int t = 0; t < 2; t++)
#pragma unroll
                for (int n = 0; n < 4; n++) mma16816(acc[t][n], al[t], b[n]);

#pragma unroll
            for (int p = 0; p < 2; p++)
                ldsm_x4t(b[2 * p][0], b[2 * p][1], b[2 * p + 1][0], b[2 * p + 1][1],
                         smb + O_BL + boff + bkb + (uint32_t)p * 32);
#pragma unroll
            for (int t = 0; t < 2; t++)
#pragma unroll
                for (int n = 0; n < 4; n++) mma16816(acc[t][n], ah[t], b[n]);
        }

        // ---- direct coalesced-sector writeout of xh fragments -------------------
#pragma unroll
        for (int t = 0; t < 2; t++)
#pragma unroll
            for (int n = 0; n < 4; n++) {
                int r = row0 + mrow + t * 16 + g;
                int c = ncol + n * 8 + tig * 2;
                if (r < N)
                    *(float2*)(g_xh + (size_t)r * 128 + c) = make_float2(acc[t][n][0], acc[t][n][1]);
                if (r + 8 < N)
                    *(float2*)(g_xh + (size_t)(r + 8) * 128 + c) = make_float2(acc[t][n][2], acc[t][n][3]);
            }

        // ---- partial scores ------------------------------------------------------
        float psi[4], psj[4];
#pragma unroll
        for (int t = 0; t < 2; t++)
#pragma unroll
            for (int h = 0; h < 2; h++) {
                float si = 0.f, sj = 0.f;
#pragma unroll
                for (int n = 0; n < 4; n++) {
                    int c = n * 8 + tig * 2;
                    float v0 = acc[t][n][h * 2 + 0];
                    float v1 = acc[t][n][h * 2 + 1];
                    si += v0 * attiq[c] + v1 * attiq[c + 1];
                    sj += v0 * attjq[c] + v1 * attjq[c + 1];
                }
                if (cg == 0) {
                    int grow = row0 + mrow + t * 16 + h * 8 + g;
                    if (grow < N) {
                        const float4* er = (const float4*)(emb + (size_t)grow * 64 + tig * 16);
#pragma unroll
                        for (int e4 = 0; e4 < 4; e4++) {
                            float4 e = er[e4];
                            si += e.x * aeiq[e4 * 4 + 0] + e.y * aeiq[e4 * 4 + 1]
                                + e.z * aeiq[e4 * 4 + 2] + e.w * aeiq[e4 * 4 + 3];
                            sj += e.x * aejq[e4 * 4 + 0] + e.y * aejq[e4 * 4 + 1]
                                + e.z * aejq[e4 * 4 + 2] + e.w * aejq[e4 * 4 + 3];
                        }
                    }
                }
                psi[t * 2 + h] = si;
                psj[t * 2 + h] = sj;
            }
#pragma unroll
        for (int r = 0; r < 4; r++) {
            psi[r] += __shfl_xor_sync(0xffffffffu, psi[r], 1);
            psi[r] += __shfl_xor_sync(0xffffffffu, psi[r], 2);
            psj[r] += __shfl_xor_sync(0xffffffffu, psj[r], 1);
            psj[r] += __shfl_xor_sync(0xffffffffu, psj[r], 2);
        }
        if (tig == 0) {
#pragma unroll
            for (int t = 0; t < 2; t++)
#pragma unroll
                for (int h = 0; h < 2; h++) {
                    int lrow = mrow + t * 16 + h * 8 + g;
                    psiA[(q * 2 + cg) * 64 + lrow] = psi[t * 2 + h];
                    psjA[(q * 2 + cg) * 64 + lrow] = psj[t * 2 + h];
                }
        }
        __syncthreads();

        if (tid < 64) {
            int grow = row0 + tid;
            if (grow < N) {
                float si0 = psiA[tid]       + psiA[64 + tid];
                float si1 = psiA[128 + tid] + psiA[192 + tid];
                float sj0 = psjA[tid]       + psjA[64 + tid];
                float sj1 = psjA[128 + tid] + psjA[192 + tid];
                *(float2*)(g_si + 2 * grow) = make_float2(si0, si1);
                *(float2*)(g_sj + 2 * grow) = make_float2(sj0, sj1);
                g_wd[grow] = 0.0;
            }
        }
        __syncthreads();   // protect A tiles + psi arrays before next iteration
    }
}

// ---------------- Kernel 2: per-edge attention, ONE packed double atomic -----
__global__ void edge_kernel(const int* __restrict__ src, const int* __restrict__ dst,
                            int E, int N)
{
    int i = blockIdx.x * blockDim.x + threadIdx.x;
    if (i >= E + N) return;
    int s, d;
    if (i < E) { s = src[i]; d = dst[i]; }
    else       { s = i - E;  d = s; }

    float2 si = *(const float2*)(g_si + 2 * s);
    float2 sj = *(const float2*)(g_sj + 2 * d);
    float a0 = si.x + sj.x;  a0 = fmaxf(a0, 0.2f * a0);
    float a1 = si.y + sj.y;  a1 = fmaxf(a1, 0.2f * a1);
    float m  = fmaxf(a0, a1);
    float e0 = __expf(a0 - m);
    float e1 = __expf(a1 - m);
    float alpha0 = __fdividef(e0, e0 + e1);     // alpha1 = 1 - alpha0

    atomicAdd(g_wd + d, (double)alpha0 + 1048576.0);   // low: sum(alpha0), high: degree
}

// ---------------- Kernel 3: out[n,d] = 0.5*(xh0*w0 + xh1*w1) ------------------
__global__ void out_kernel(float* __restrict__ out, int N)
{
    int i = blockIdx.x * blockDim.x + threadIdx.x;
    if (i >= N * 16) return;
    int n  = i >> 4;
    int d4 = (i & 15) << 2;
    double v   = g_wd[n];
    double deg = floor(v * 9.5367431640625e-07);       // v / 2^20
    float  w0  = (float)(v - deg * 1048576.0);
    float  w1  = (float)deg - w0;
    float4 a = *(const float4*)(g_xh + (size_t)n * 128 + d4);
    float4 b = *(const float4*)(g_xh + (size_t)n * 128 + 64 + d4);
    float4 o;
    o.x = 0.5f * (a.x * w0 + b.x * w1);
    o.y = 0.5f * (a.y * w0 + b.y * w1);
    o.z = 0.5f * (a.z * w0 + b.z * w1);
    o.w = 0.5f * (a.w * w0 + b.w * w1);
    ((float4*)out)[i] = o;
}

// ---------------- launcher ---------------------------------------------------
extern "C" void kernel_launch(void* const* d_in, const int* in_sizes, int n_in,
                              void* d_out, int out_size)
{
    const float* x    = (const float*)d_in[0];
    const float* emb  = (const float*)d_in[1];
    const float* W    = (const float*)d_in[2];
    const float* ai   = (const float*)d_in[3];
    const float* aj   = (const float*)d_in[4];
    const float* aei  = (const float*)d_in[5];
    const float* aej  = (const float*)d_in[6];
    const int*   esrc = (const int*)d_in[7];
    const int*   edst = (const int*)d_in[8];
    float* out = (float*)d_out;

    const int N = in_sizes[0] / 128;   // 50000
    const int E = in_sizes[7];         // 1600000
    const int ntiles = (N + 63) / 64;
    int grid = 296;                    // 2 CTAs/SM x 148 SMs
    if (grid > ntiles) grid = ntiles;

    cudaFuncSetAttribute(fused_gemm_kernel,
                         cudaFuncAttributeMaxDynamicSharedMemorySize, SMEM_TOTAL);

    wsplit_kernel<<<16, 256>>>(W);
    fused_gemm_kernel<<<grid, 256, SMEM_TOTAL>>>(x, emb, ai, aj, aei, aej, N, ntiles);
    edge_kernel<<<(E + N + 255) / 256, 256>>>(esrc, edst, E, N);
    out_kernel<<<(N * 16 + 255) / 256, 256>>>(out, N);
}

// round 7
// speedup vs baseline: 1.6049x; 1.0162x over previous
#include <cuda_runtime.h>
#include <cuda_bf16.h>
#include <cstdint>
#include <math.h>

// ---------------- scratch (device globals; no allocations allowed) ----------
#define NMAX 50000
__device__ float  g_xh[(size_t)NMAX * 128];  // [N, H*D] = [N,128]
__device__ float  g_s [NMAX * 4];            // (si0, si1, sj0, sj1) per node
__device__ double g_wd[NMAX];                // packed: deg*2^20 + sum(alpha0), excl self
__device__ __nv_bfloat16 g_wh[128 * 128];    // W hi, natural [k][n]
__device__ __nv_bfloat16 g_wl[128 * 128];    // W lo

// ---------------- PTX helpers (base sm_103 target) --------------------------
__device__ __forceinline__ uint32_t smem_u32(const void* p) {
    uint32_t a;
    asm("{ .reg .u64 t; cvta.to.shared.u64 t, %1; cvt.u32.u64 %0, t; }"
        : "=r"(a) : "l"(p));
    return a;
}
__device__ __forceinline__ void ldsm_x4(uint32_t& r0, uint32_t& r1,
                                        uint32_t& r2, uint32_t& r3, uint32_t addr) {
    asm volatile("ldmatrix.sync.aligned.m8n8.x4.shared.b16 {%0,%1,%2,%3}, [%4];"
                 : "=r"(r0), "=r"(r1), "=r"(r2), "=r"(r3) : "r"(addr));
}
__device__ __forceinline__ void ldsm_x4t(uint32_t& r0, uint32_t& r1,
                                         uint32_t& r2, uint32_t& r3, uint32_t addr) {
    asm volatile("ldmatrix.sync.aligned.m8n8.x4.trans.shared.b16 {%0,%1,%2,%3}, [%4];"
                 : "=r"(r0), "=r"(r1), "=r"(r2), "=r"(r3) : "r"(addr));
}
__device__ __forceinline__ void mma16816(float* c, const uint32_t* a, const uint32_t* b) {
    asm volatile(
        "mma.sync.aligned.m16n8k16.row.col.f32.bf16.bf16.f32 "
        "{%0,%1,%2,%3}, {%4,%5,%6,%7}, {%8,%9}, {%0,%1,%2,%3};"
        : "+f"(c[0]), "+f"(c[1]), "+f"(c[2]), "+f"(c[3])
        : "r"(a[0]), "r"(a[1]), "r"(a[2]), "r"(a[3]), "r"(b[0]), "r"(b[1]));
}

__device__ __forceinline__ void split4(float4 v, uint2& hi, uint2& lo) {
    __nv_bfloat16 hx = __float2bfloat16(v.x), hy = __float2bfloat16(v.y);
    __nv_bfloat16 hz = __float2bfloat16(v.z), hw = __float2bfloat16(v.w);
    __nv_bfloat16 lx = __float2bfloat16(v.x - __bfloat162float(hx));
    __nv_bfloat16 ly = __float2bfloat16(v.y - __bfloat162float(hy));
    __nv_bfloat16 lz = __float2bfloat16(v.z - __bfloat162float(hz));
    __nv_bfloat16 lw = __float2bfloat16(v.w - __bfloat162float(hw));
    hi.x = (uint32_t)__bfloat16_as_ushort(hx) | ((uint32_t)__bfloat16_as_ushort(hy) << 16);
    hi.y = (uint32_t)__bfloat16_as_ushort(hz) | ((uint32_t)__bfloat16_as_ushort(hw) << 16);
    lo.x = (uint32_t)__bfloat16_as_ushort(lx) | ((uint32_t)__bfloat16_as_ushort(ly) << 16);
    lo.y = (uint32_t)__bfloat16_as_ushort(lz) | ((uint32_t)__bfloat16_as_ushort(lw) << 16);
}

// ---------------- SMEM layout (bytes) ----------------------------------------
#define KP 136
#define O_ATT   0                       // 512 floats = 2048B
#define O_PSI   2048                    // 1024B
#define O_PSJ   3072                    // 1024B
#define O_AH    4096                    // A hi  [64 m][KP k]  = 17408B
#define O_AL    (O_AH + 17408)
#define O_BH    (O_AL + 17408)          // B hi  [128 k][KP n] = 34816B
#define O_BL    (O_BH + 34816)
#define SMEM_TOTAL (O_BL + 34816)       // 108544 -> 2 CTAs/SM

// ---------------- Kernel 0: precompute W bf16 hi/lo split --------------------
__global__ void wsplit_kernel(const float* __restrict__ W)
{
    int i = blockIdx.x * blockDim.x + threadIdx.x;   // over 4096 float4s
    if (i >= 128 * 128 / 4) return;
    float4 v = ((const float4*)W)[i];
    uint2 hi, lo;
    split4(v, hi, lo);
    ((uint2*)g_wh)[i] = hi;
    ((uint2*)g_wl)[i] = lo;
}

// ---------------- Kernel 1: persistent fused GEMM + scores -------------------
__global__ __launch_bounds__(256, 2)
void fused_gemm_kernel(const float* __restrict__ x,
                       const float* __restrict__ emb,
                       const float* __restrict__ ai,  const float* __restrict__ aj,
                       const float* __restrict__ aei, const float* __restrict__ aej,
                       int N, int ntiles)
{
    extern __shared__ char sm[];
    const uint32_t smb = smem_u32(sm);
    const int tid = threadIdx.x;
    const int wid = tid >> 5;
    const int lid = tid & 31;

    // ---- stage B ONCE: pure copy of precomputed split (uint4 = 8 bf16) -------
#pragma unroll
    for (int i = 0; i < 8; i++) {
        int idx = tid + i * 256;            // over 2048 uint4s
        int k = idx >> 4, n = (idx & 15) * 8;
        uint32_t off = (uint32_t)(k * KP + n) * 2;
        *(uint4*)(sm + O_BH + off) = ((const uint4*)g_wh)[idx];
        *(uint4*)(sm + O_BL + off) = ((const uint4*)g_wl)[idx];
    }
    // ---- stage attention vectors ---------------------------------------------
    {
        float* satt = (float*)(sm + O_ATT);
#pragma unroll
        for (int i = 0; i < 2; i++) {
            int t = tid + i * 256;
            float v;
            if      (t < 128) v = ai [t];
            else if (t < 256) v = aj [t - 128];
            else if (t < 384) v = aei[t - 256];
            else              v = aej[t - 384];
            satt[t] = v;
        }
    }

    // warp tile coords (constant across tiles)
    const int mrow = (wid & 1) * 32;
    const int ncol = (wid >> 1) * 32;
    const int q    = ncol >> 6;
    const int cg   = (ncol >> 5) & 1;
    const int g    = lid >> 2, tig = lid & 3;

    const int l15 = lid & 15;
    const int lh8 = (lid >> 4) * 8;
    const uint32_t aoff = (uint32_t)((mrow + l15) * KP + lh8) * 2;
    const int bkr = ((lid >> 3) & 1) * 8 + (lid & 7);
    const int bnc = (lid >> 4) * 8;
    const uint32_t boff = (uint32_t)(bkr * KP + ncol + bnc) * 2;

    const float* satt = (const float*)(sm + O_ATT);
    const float* attiq = satt + q * 64 + cg * 32;
    const float* attjq = satt + 128 + q * 64 + cg * 32;
    const float* aeiq  = satt + 256 + q * 64 + tig * 16;
    const float* aejq  = satt + 384 + q * 64 + tig * 16;
    float* psiA = (float*)(sm + O_PSI);
    float* psjA = (float*)(sm + O_PSJ);

    for (int tile = blockIdx.x; tile < ntiles; tile += gridDim.x) {
        const int row0 = tile * 64;

        // ---- stage A tile (bf16 hi/lo split) ----------------------------------
#pragma unroll
        for (int i = 0; i < 8; i++) {
            int idx = tid + i * 256;
            int r = idx >> 5, c = (idx & 31) * 4;
            float4 v = make_float4(0.f, 0.f, 0.f, 0.f);
            if (row0 + r < N) v = *(const float4*)(x + (size_t)(row0 + r) * 128 + c);
            uint2 hi, lo;
            split4(v, hi, lo);
            uint32_t off = (uint32_t)(r * KP + c) * 2;
            *(uint2*)(sm + O_AH + off) = hi;
            *(uint2*)(sm + O_AL + off) = lo;
        }
        __syncthreads();

        // ---- MMA ----------------------------------------------------------------
        float acc[2][4][4];
#pragma unroll
        for (int t = 0; t < 2; t++)
#pragma unroll
            for (int n = 0; n < 4; n++)
#pragma unroll
                for (int k = 0; k < 4; k++) acc[t][n][k] = 0.f;

#pragma unroll
        for (int ks = 0; ks < 8; ks++) {
            const uint32_t akb = (uint32_t)ks * 32;
            const uint32_t bkb = (uint32_t)ks * (16 * KP * 2);
            uint32_t ah[2][4], al[2][4], b[4][2];

#pragma unroll
            for (int t = 0; t < 2; t++)
                ldsm_x4(ah[t][0], ah[t][1], ah[t][2], ah[t][3],
                        smb + O_AH + aoff + (uint32_t)t * (16 * KP * 2) + akb);
#pragma unroll
            for (int p = 0; p < 2; p++)
                ldsm_x4t(b[2 * p][0], b[2 * p][1], b[2 * p + 1][0], b[2 * p + 1][1],
                         smb + O_BH + boff + bkb + (uint32_t)p * 32);
#pragma unroll
            for (int t = 0; t < 2; t++)
#pragma unroll
                for (int n = 0; n < 4; n++) mma16816(acc[t][n], ah[t], b[n]);

#pragma unroll
            for (int t = 0; t < 2; t++)
                ldsm_x4(al[t][0], al[t][1], al[t][2], al[t][3],
                        smb + O_AL + aoff + (uint32_t)t * (16 * KP * 2) + akb);
#pragma unroll
            for (int t = 0; t < 2; t++)
#pragma unroll
                for (int n = 0; n < 4; n++) mma16816(acc[t][n], al[t], b[n]);

#pragma unroll
            for (int p = 0; p < 2; p++)
                ldsm_x4t(b[2 * p][0], b[2 * p][1], b[2 * p + 1][0], b[2 * p + 1][1],
                         smb + O_BL + boff + bkb + (uint32_t)p * 32);
#pragma unroll
            for (int t = 0; t < 2; t++)
#pragma unroll
                for (int n = 0; n < 4; n++) mma16816(acc[t][n], ah[t], b[n]);
        }

        // ---- direct coalesced-sector writeout of xh fragments -------------------
#pragma unroll
        for (int t = 0; t < 2; t++)
#pragma unroll
            for (int n = 0; n < 4; n++) {
                int r = row0 + mrow + t * 16 + g;
                int c = ncol + n * 8 + tig * 2;
                if (r < N)
                    *(float2*)(g_xh + (size_t)r * 128 + c) = make_float2(acc[t][n][0], acc[t][n][1]);
                if (r + 8 < N)
                    *(float2*)(g_xh + (size_t)(r + 8) * 128 + c) = make_float2(acc[t][n][2], acc[t][n][3]);
            }

        // ---- partial scores ------------------------------------------------------
        float psi[4], psj[4];
#pragma unroll
        for (int t = 0; t < 2; t++)
#pragma unroll
            for (int h = 0; h < 2; h++) {
                float si = 0.f, sj = 0.f;
#pragma unroll
                for (int n = 0; n < 4; n++) {
                    int c = n * 8 + tig * 2;
                    float v0 = acc[t][n][h * 2 + 0];
                    float v1 = acc[t][n][h * 2 + 1];
                    si += v0 * attiq[c] + v1 * attiq[c + 1];
                    sj += v0 * attjq[c] + v1 * attjq[c + 1];
                }
                if (cg == 0) {
                    int grow = row0 + mrow + t * 16 + h * 8 + g;
                    if (grow < N) {
                        const float4* er = (const float4*)(emb + (size_t)grow * 64 + tig * 16);
#pragma unroll
                        for (int e4 = 0; e4 < 4; e4++) {
                            float4 e = er[e4];
                            si += e.x * aeiq[e4 * 4 + 0] + e.y * aeiq[e4 * 4 + 1]
                                + e.z * aeiq[e4 * 4 + 2] + e.w * aeiq[e4 * 4 + 3];
                            sj += e.x * aejq[e4 * 4 + 0] + e.y * aejq[e4 * 4 + 1]
                                + e.z * aejq[e4 * 4 + 2] + e.w * aejq[e4 * 4 + 3];
                        }
                    }
                }
                psi[t * 2 + h] = si;
                psj[t * 2 + h] = sj;
            }
#pragma unroll
        for (int r = 0; r < 4; r++) {
            psi[r] += __shfl_xor_sync(0xffffffffu, psi[r], 1);
            psi[r] += __shfl_xor_sync(0xffffffffu, psi[r], 2);
            psj[r] += __shfl_xor_sync(0xffffffffu, psj[r], 1);
            psj[r] += __shfl_xor_sync(0xffffffffu, psj[r], 2);
        }
        if (tig == 0) {
#pragma unroll
            for (int t = 0; t < 2; t++)
#pragma unroll
                for (int h = 0; h < 2; h++) {
                    int lrow = mrow + t * 16 + h * 8 + g;
                    psiA[(q * 2 + cg) * 64 + lrow] = psi[t * 2 + h];
                    psjA[(q * 2 + cg) * 64 + lrow] = psj[t * 2 + h];
                }
        }
        __syncthreads();

        if (tid < 64) {
            int grow = row0 + tid;
            if (grow < N) {
                float si0 = psiA[tid]       + psiA[64 + tid];
                float si1 = psiA[128 + tid] + psiA[192 + tid];
                float sj0 = psjA[tid]       + psjA[64 + tid];
                float sj1 = psjA[128 + tid] + psjA[192 + tid];
                *(float4*)(g_s + 4 * grow) = make_float4(si0, si1, sj0, sj1);
                g_wd[grow] = 0.0;
            }
        }
        __syncthreads();   // protect A tiles + psi arrays before next iteration
    }
}

// ---------------- Kernel 2: per-edge attention, 2 edges/thread ---------------
__global__ void edge_kernel(const int* __restrict__ src, const int* __restrict__ dst,
                            int Ehalf)
{
    int i = blockIdx.x * blockDim.x + threadIdx.x;
    if (i >= Ehalf) return;
    int2 s2 = ((const int2*)src)[i];
    int2 d2 = ((const int2*)dst)[i];

    float4 sa = *(const float4*)(g_s + 4 * s2.x);
    float4 da = *(const float4*)(g_s + 4 * d2.x);
    float4 sb = *(const float4*)(g_s + 4 * s2.y);
    float4 db = *(const float4*)(g_s + 4 * d2.y);

    // edge a
    {
        float a0 = sa.x + da.z;  a0 = fmaxf(a0, 0.2f * a0);
        float a1 = sa.y + da.w;  a1 = fmaxf(a1, 0.2f * a1);
        float m  = fmaxf(a0, a1);
        float e0 = __expf(a0 - m);
        float e1 = __expf(a1 - m);
        float alpha0 = __fdividef(e0, e0 + e1);
        atomicAdd(g_wd + d2.x, (double)alpha0 + 1048576.0);
    }
    // edge b
    {
        float a0 = sb.x + db.z;  a0 = fmaxf(a0, 0.2f * a0);
        float a1 = sb.y + db.w;  a1 = fmaxf(a1, 0.2f * a1);
        float m  = fmaxf(a0, a1);
        float e0 = __expf(a0 - m);
        float e1 = __expf(a1 - m);
        float alpha0 = __fdividef(e0, e0 + e1);
        atomicAdd(g_wd + d2.y, (double)alpha0 + 1048576.0);
    }
}

// ---------------- Kernel 3: out = 0.5*(xh0*w0 + xh1*w1), self-loop inline ----
__global__ void out_kernel(float* __restrict__ out, int N)
{
    int i = blockIdx.x * blockDim.x + threadIdx.x;   // over N*8 items
    if (i >= N * 8) return;
    int n  = i >> 3;
    int d8 = (i & 7) << 3;

    // self-loop contribution (same math as edge with s=d=n)
    float4 ss = *(const float4*)(g_s + 4 * n);
    float a0 = ss.x + ss.z;  a0 = fmaxf(a0, 0.2f * a0);
    float a1 = ss.y + ss.w;  a1 = fmaxf(a1, 0.2f * a1);
    float m  = fmaxf(a0, a1);
    float e0 = __expf(a0 - m);
    float e1 = __expf(a1 - m);
    float aself = __fdividef(e0, e0 + e1);

    double v   = g_wd[n];
    double deg = floor(v * 9.5367431640625e-07);       // v / 2^20
    float  w0  = (float)(v - deg * 1048576.0) + aself;
    float  w1  = ((float)deg + 1.0f) - w0;

    const float* xr = g_xh + (size_t)n * 128;
    float4 av0 = *(const float4*)(xr + d8);
    float4 av1 = *(const float4*)(xr + d8 + 4);
    float4 bv0 = *(const float4*)(xr + 64 + d8);
    float4 bv1 = *(const float4*)(xr + 64 + d8 + 4);

    float4 o0, o1;
    o0.x = 0.5f * (av0.x * w0 + bv0.x * w1);
    o0.y = 0.5f * (av0.y * w0 + bv0.y * w1);
    o0.z = 0.5f * (av0.z * w0 + bv0.z * w1);
    o0.w = 0.5f * (av0.w * w0 + bv0.w * w1);
    o1.x = 0.5f * (av1.x * w0 + bv1.x * w1);
    o1.y = 0.5f * (av1.y * w0 + bv1.y * w1);
    o1.z = 0.5f * (av1.z * w0 + bv1.z * w1);
    o1.w = 0.5f * (av1.w * w0 + bv1.w * w1);
    *(float4*)(out + (size_t)n * 64 + d8)     = o0;
    *(float4*)(out + (size_t)n * 64 + d8 + 4) = o1;
}

// ---------------- launcher ---------------------------------------------------
extern "C" void kernel_launch(void* const* d_in, const int* in_sizes, int n_in,
                              void* d_out, int out_size)
{
    const float* x    = (const float*)d_in[0];
    const float* emb  = (const float*)d_in[1];
    const float* W    = (const float*)d_in[2];
    const float* ai   = (const float*)d_in[3];
    const float* aj   = (const float*)d_in[4];
    const float* aei  = (const float*)d_in[5];
    const float* aej  = (const float*)d_in[6];
    const int*   esrc = (const int*)d_in[7];
    const int*   edst = (const int*)d_in[8];
    float* out = (float*)d_out;

    const int N = in_sizes[0] / 128;   // 50000
    const int E = in_sizes[7];         // 1600000 (even)
    const int ntiles = (N + 63) / 64;
    int grid = 296;                    // 2 CTAs/SM x 148 SMs
    if (grid > ntiles) grid = ntiles;

    cudaFuncSetAttribute(fused_gemm_kernel,
                         cudaFuncAttributeMaxDynamicSharedMemorySize, SMEM_TOTAL);

    wsplit_kernel<<<16, 256>>>(W);
    fused_gemm_kernel<<<grid, 256, SMEM_TOTAL>>>(x, emb, ai, aj, aei, aej, N, ntiles);
    const int Ehalf = E / 2;
    edge_kernel<<<(Ehalf + 255) / 256, 256>>>(esrc, edst, Ehalf);
    out_kernel<<<(N * 8 + 255) / 256, 256>>>(out, N);
}